// round 7
// baseline (speedup 1.0000x reference)
#include <cuda_runtime.h>
#include <math.h>

#define HD 256      // hidden dim
#define BB 2        // batch
#define LL 512      // seq len (L1 == L2)
#define NHEAD 8
#define DHEAD 32

// ---------------- scratch (device globals; no allocation) ----------------
__device__ float g_q [BB*LL*HD];                 // 1 MB
__device__ float g_k [BB*LL*HD];                 // 1 MB
__device__ float g_h1[BB*LL*HD];                 // 1 MB (includes +b1)
__device__ float g_h2[BB*LL*HD];                 // 1 MB
__device__ float g_logits[(size_t)BB*NHEAD*LL*LL]; // 16 MB; reused for match partials

// ---------------- packed fp32x2 helpers (Blackwell) ----------------
typedef unsigned long long u64p;

__device__ __forceinline__ void f2_unpack(u64p p, float& lo, float& hi) {
    asm("mov.b64 {%0, %1}, %2;" : "=f"(lo), "=f"(hi) : "l"(p));
}
__device__ __forceinline__ u64p f2_fma(u64p a, u64p b, u64p c) {
    u64p d; asm("fma.rn.f32x2 %0, %1, %2, %3;" : "=l"(d) : "l"(a), "l"(b), "l"(c)); return d;
}
__device__ __forceinline__ u64p f2_add(u64p a, u64p b) {
    u64p d; asm("add.rn.f32x2 %0, %1, %2;" : "=l"(d) : "l"(a), "l"(b)); return d;
}
__device__ __forceinline__ u64p f2_relu(u64p x) {
    float lo, hi; f2_unpack(x, lo, hi);
    lo = fmaxf(lo, 0.0f); hi = fmaxf(hi, 0.0f);
    u64p r; asm("mov.b64 %0, {%1, %2};" : "=l"(r) : "f"(lo), "f"(hi)); return r;
}

// =========================================================================
// K1: projections.  job z: 0=q 1=k 2=h1(+b1) 3=h2
// Block tile 64i x 128j, 128 threads, per-thread 8i x 8j (i-packed pairs).
// A natural pairs (no dup), W duplicated (amortized over Ti=8).
// grid (2, 16, 4) = 128 blocks.
// =========================================================================
__global__ __launch_bounds__(128) void proj_kernel(
    const float* __restrict__ e1, const float* __restrict__ e2,
    const float* __restrict__ ipw, const float* __restrict__ ipb,
    const float* __restrict__ W1,  const float* __restrict__ b1)
{
    const int job = blockIdx.z;
    const float* A; const float* W; const float* bias; int ldw; float* C;
    if (job == 0)      { A = e1; W = ipw;           bias = ipb;      ldw = HD;   C = g_q;  }
    else if (job == 1) { A = e2; W = ipw + HD*HD;   bias = ipb + HD; ldw = HD;   C = g_k;  }
    else if (job == 2) { A = e1; W = W1;            bias = b1;       ldw = 2*HD; C = g_h1; }
    else               { A = e2; W = W1 + HD;       bias = nullptr;  ldw = 2*HD; C = g_h2; }

    const int i0 = blockIdx.y * 64;
    const int j0 = blockIdx.x * 128;

    __shared__ __align__(16) float sA [32][68];    // [kk][i], 64 used
    __shared__ __align__(16) float sWd[32][260];   // [kk][2j], 256 used (dup)

    const int tid = threadIdx.x;
    const int ty = tid >> 4;       // 0..7  -> 8 rows (4 pairs)
    const int tx = tid & 15;       // 0..15 -> 8 cols

    u64p acc[4][8] = {};

    for (int k0 = 0; k0 < HD; k0 += 32) {
        float4 va[4], vw[8];
        int arow[4], ak[4], wrow[8], wk[8];
#pragma unroll
        for (int r = 0; r < 4; r++) {
            int p = tid + r * 128;
            arow[r] = p >> 3; ak[r] = (p & 7) << 2;
            va[r] = *(const float4*)&A[(size_t)(i0 + arow[r]) * HD + k0 + ak[r]];
        }
#pragma unroll
        for (int r = 0; r < 8; r++) {
            int p = tid + r * 128;
            wrow[r] = p >> 3; wk[r] = (p & 7) << 2;
            vw[r] = *(const float4*)&W[(size_t)(j0 + wrow[r]) * ldw + k0 + wk[r]];
        }
        __syncthreads();
#pragma unroll
        for (int r = 0; r < 4; r++) {
            sA[ak[r]+0][arow[r]] = va[r].x; sA[ak[r]+1][arow[r]] = va[r].y;
            sA[ak[r]+2][arow[r]] = va[r].z; sA[ak[r]+3][arow[r]] = va[r].w;
        }
#pragma unroll
        for (int r = 0; r < 8; r++) {
            *(float2*)&sWd[wk[r]+0][2*wrow[r]] = make_float2(vw[r].x, vw[r].x);
            *(float2*)&sWd[wk[r]+1][2*wrow[r]] = make_float2(vw[r].y, vw[r].y);
            *(float2*)&sWd[wk[r]+2][2*wrow[r]] = make_float2(vw[r].z, vw[r].z);
            *(float2*)&sWd[wk[r]+3][2*wrow[r]] = make_float2(vw[r].w, vw[r].w);
        }
        __syncthreads();

#pragma unroll
        for (int kk = 0; kk < 32; kk++) {
            const ulonglong2 a01 = *(const ulonglong2*)&sA[kk][ty*8];
            const ulonglong2 a23 = *(const ulonglong2*)&sA[kk][ty*8 + 4];
            const ulonglong2 w01 = *(const ulonglong2*)&sWd[kk][tx*16];
            const ulonglong2 w23 = *(const ulonglong2*)&sWd[kk][tx*16 + 4];
            const ulonglong2 w45 = *(const ulonglong2*)&sWd[kk][tx*16 + 8];
            const ulonglong2 w67 = *(const ulonglong2*)&sWd[kk][tx*16 + 12];
            u64p a[4] = {a01.x, a01.y, a23.x, a23.y};
            u64p w[8] = {w01.x, w01.y, w23.x, w23.y, w45.x, w45.y, w67.x, w67.y};
#pragma unroll
            for (int p = 0; p < 4; p++)
#pragma unroll
                for (int j = 0; j < 8; j++)
                    acc[p][j] = f2_fma(a[p], w[j], acc[p][j]);
        }
        __syncthreads();
    }

    float bv[8] = {0,0,0,0,0,0,0,0};
    if (bias) {
        float4 b0 = *(const float4*)&bias[j0 + tx*8];
        float4 b1v = *(const float4*)&bias[j0 + tx*8 + 4];
        bv[0]=b0.x; bv[1]=b0.y; bv[2]=b0.z; bv[3]=b0.w;
        bv[4]=b1v.x; bv[5]=b1v.y; bv[6]=b1v.z; bv[7]=b1v.w;
    }
#pragma unroll
    for (int p = 0; p < 4; p++) {
        float lo[8], hi[8];
#pragma unroll
        for (int j = 0; j < 8; j++) f2_unpack(acc[p][j], lo[j], hi[j]);
        const int r0 = i0 + ty*8 + 2*p;
        float* c0p = &C[(size_t)(r0+0) * HD + j0 + tx*8];
        float* c1p = &C[(size_t)(r0+1) * HD + j0 + tx*8];
        *(float4*)&c0p[0] = make_float4(lo[0]+bv[0], lo[1]+bv[1], lo[2]+bv[2], lo[3]+bv[3]);
        *(float4*)&c0p[4] = make_float4(lo[4]+bv[4], lo[5]+bv[5], lo[6]+bv[6], lo[7]+bv[7]);
        *(float4*)&c1p[0] = make_float4(hi[0]+bv[0], hi[1]+bv[1], hi[2]+bv[2], hi[3]+bv[3]);
        *(float4*)&c1p[4] = make_float4(hi[4]+bv[4], hi[5]+bv[5], hi[6]+bv[6], hi[7]+bv[7]);
    }
}

// =========================================================================
// K2: logits[b,h,i,j] = (1/sqrt(32)) * sum_d q*k
// Block tile 64i x 128j, 128 threads, 8i x 8j/thread, K=32 single chunk.
// grid (4, 8, 16) = 512 blocks.
// =========================================================================
__global__ __launch_bounds__(128) void logits_kernel()
{
    const int bh = blockIdx.z;
    const int b  = bh >> 3, h = bh & 7;
    const float* Q  = g_q + (size_t)b * LL * HD + h * DHEAD;
    const float* Kp = g_k + (size_t)b * LL * HD + h * DHEAD;
    float* C = g_logits + (size_t)bh * LL * LL;

    const int i0 = blockIdx.y * 64;
    const int j0 = blockIdx.x * 128;

    __shared__ __align__(16) float sQ [32][68];
    __shared__ __align__(16) float sKd[32][260];

    const int tid = threadIdx.x;
    const int ty = tid >> 4;
    const int tx = tid & 15;

    {
        float4 vq[4], vk[8];
        int qrow[4], qk[4], krow[8], kk4[8];
#pragma unroll
        for (int r = 0; r < 4; r++) {
            int p = tid + r * 128;
            qrow[r] = p >> 3; qk[r] = (p & 7) << 2;
            vq[r] = *(const float4*)&Q[(size_t)(i0 + qrow[r]) * HD + qk[r]];
        }
#pragma unroll
        for (int r = 0; r < 8; r++) {
            int p = tid + r * 128;
            krow[r] = p >> 3; kk4[r] = (p & 7) << 2;
            vk[r] = *(const float4*)&Kp[(size_t)(j0 + krow[r]) * HD + kk4[r]];
        }
#pragma unroll
        for (int r = 0; r < 4; r++) {
            sQ[qk[r]+0][qrow[r]] = vq[r].x; sQ[qk[r]+1][qrow[r]] = vq[r].y;
            sQ[qk[r]+2][qrow[r]] = vq[r].z; sQ[qk[r]+3][qrow[r]] = vq[r].w;
        }
#pragma unroll
        for (int r = 0; r < 8; r++) {
            *(float2*)&sKd[kk4[r]+0][2*krow[r]] = make_float2(vk[r].x, vk[r].x);
            *(float2*)&sKd[kk4[r]+1][2*krow[r]] = make_float2(vk[r].y, vk[r].y);
            *(float2*)&sKd[kk4[r]+2][2*krow[r]] = make_float2(vk[r].z, vk[r].z);
            *(float2*)&sKd[kk4[r]+3][2*krow[r]] = make_float2(vk[r].w, vk[r].w);
        }
    }
    __syncthreads();

    u64p acc[4][8] = {};
#pragma unroll
    for (int kk = 0; kk < 32; kk++) {
        const ulonglong2 a01 = *(const ulonglong2*)&sQ[kk][ty*8];
        const ulonglong2 a23 = *(const ulonglong2*)&sQ[kk][ty*8 + 4];
        const ulonglong2 w01 = *(const ulonglong2*)&sKd[kk][tx*16];
        const ulonglong2 w23 = *(const ulonglong2*)&sKd[kk][tx*16 + 4];
        const ulonglong2 w45 = *(const ulonglong2*)&sKd[kk][tx*16 + 8];
        const ulonglong2 w67 = *(const ulonglong2*)&sKd[kk][tx*16 + 12];
        u64p a[4] = {a01.x, a01.y, a23.x, a23.y};
        u64p w[8] = {w01.x, w01.y, w23.x, w23.y, w45.x, w45.y, w67.x, w67.y};
#pragma unroll
        for (int p = 0; p < 4; p++)
#pragma unroll
            for (int j = 0; j < 8; j++)
                acc[p][j] = f2_fma(a[p], w[j], acc[p][j]);
    }

    const float scale = 0.1767766952966369f; // 1/sqrt(32)
#pragma unroll
    for (int p = 0; p < 4; p++) {
        float lo[8], hi[8];
#pragma unroll
        for (int j = 0; j < 8; j++) f2_unpack(acc[p][j], lo[j], hi[j]);
        const int r0 = i0 + ty*8 + 2*p;
        float* c0p = &C[(size_t)(r0+0) * LL + j0 + tx*8];
        float* c1p = &C[(size_t)(r0+1) * LL + j0 + tx*8];
        *(float4*)&c0p[0] = make_float4(lo[0]*scale, lo[1]*scale, lo[2]*scale, lo[3]*scale);
        *(float4*)&c0p[4] = make_float4(lo[4]*scale, lo[5]*scale, lo[6]*scale, lo[7]*scale);
        *(float4*)&c1p[0] = make_float4(hi[0]*scale, hi[1]*scale, hi[2]*scale, hi[3]*scale);
        *(float4*)&c1p[4] = make_float4(hi[4]*scale, hi[5]*scale, hi[6]*scale, hi[7]*scale);
    }
}

// =========================================================================
// K3: softmax + head-mean.  One block per (b,i); warp h owns head h's row.
// =========================================================================
__global__ __launch_bounds__(256) void softmax_mean_kernel(float* __restrict__ out)
{
    const int b = blockIdx.x >> 9;
    const int i = blockIdx.x & 511;
    const int wid  = threadIdx.x >> 5;
    const int lane = threadIdx.x & 31;

    __shared__ float p[8][512];

    const float* row = g_logits + ((size_t)(b*8 + wid) * LL + i) * LL;

    float v[16];
    float mx = -1e30f;
#pragma unroll
    for (int r = 0; r < 16; r++) {
        v[r] = row[lane + 32*r];
        mx = fmaxf(mx, v[r]);
    }
#pragma unroll
    for (int o = 16; o; o >>= 1) mx = fmaxf(mx, __shfl_xor_sync(0xffffffffu, mx, o));

    float s = 0.0f;
#pragma unroll
    for (int r = 0; r < 16; r++) { v[r] = __expf(v[r] - mx); s += v[r]; }
#pragma unroll
    for (int o = 16; o; o >>= 1) s += __shfl_xor_sync(0xffffffffu, s, o);
    const float inv = 1.0f / s;

#pragma unroll
    for (int r = 0; r < 16; r++) p[wid][lane + 32*r] = v[r] * inv;

    __syncthreads();

    const int t = threadIdx.x;
    const size_t o = ((size_t)b * LL + i) * LL;
#pragma unroll
    for (int jj = 0; jj < 2; jj++) {
        int j = t + jj * 256;
        float a = 0.0f;
#pragma unroll
        for (int h = 0; h < 8; h++) a += p[h][j];
        out[o + j] = a * 0.125f;
    }
}

// =========================================================================
// K4: match partials over 4 channel-splits of 64.
// P[((s*BB+b)*LL+i)*LL+j] = sum_{c in split} relu(h1[i,c]+h2[j,c])*w2[c]
// Block tile 128i x 64j, 256 threads, 8i x 4j/thread (i-packed pairs).
// A natural pairs, B duplicated, w2 duplicated. grid (8, 4, 8) = 256 blocks.
// =========================================================================
__global__ __launch_bounds__(256) void match_partial_kernel(
    const float* __restrict__ W2, float* __restrict__ P)
{
    const int bz = blockIdx.z;
    const int b  = bz >> 2;
    const int s  = bz & 3;
    const int i0 = blockIdx.y * 128;
    const int j0 = blockIdx.x * 64;
    const int c0 = s * 64;

    const float* A  = g_h1 + (size_t)b * LL * HD;
    const float* Bm = g_h2 + (size_t)b * LL * HD;

    __shared__ __align__(16) float sA [32][132];  // [kk][i], 128 used (natural)
    __shared__ __align__(16) float sBd[32][132];  // [kk][2j], 128 used (dup)
    __shared__ __align__(16) float2 sw2d[64];     // (w,w)

    const int tid = threadIdx.x;
    const int ty = tid >> 4;       // 0..15 -> 8 rows (4 pairs)
    const int tx = tid & 15;       // 0..15 -> 4 cols

    if (tid < 64) { float w = W2[c0 + tid]; sw2d[tid] = make_float2(w, w); }
    const u64p* swd = (const u64p*)sw2d;

    u64p acc[4][4] = {};

    for (int kc = 0; kc < 64; kc += 32) {
        const int k0 = c0 + kc;
        float4 va[4], vb[2];
        int arow[4], ak[4], brow[2], bk[2];
#pragma unroll
        for (int r = 0; r < 4; r++) {
            int p = tid + r * 256;
            arow[r] = p >> 3; ak[r] = (p & 7) << 2;
            va[r] = *(const float4*)&A[(size_t)(i0 + arow[r]) * HD + k0 + ak[r]];
        }
#pragma unroll
        for (int r = 0; r < 2; r++) {
            int p = tid + r * 256;
            brow[r] = p >> 3; bk[r] = (p & 7) << 2;
            vb[r] = *(const float4*)&Bm[(size_t)(j0 + brow[r]) * HD + k0 + bk[r]];
        }
        __syncthreads();
#pragma unroll
        for (int r = 0; r < 4; r++) {
            sA[ak[r]+0][arow[r]] = va[r].x; sA[ak[r]+1][arow[r]] = va[r].y;
            sA[ak[r]+2][arow[r]] = va[r].z; sA[ak[r]+3][arow[r]] = va[r].w;
        }
#pragma unroll
        for (int r = 0; r < 2; r++) {
            *(float2*)&sBd[bk[r]+0][2*brow[r]] = make_float2(vb[r].x, vb[r].x);
            *(float2*)&sBd[bk[r]+1][2*brow[r]] = make_float2(vb[r].y, vb[r].y);
            *(float2*)&sBd[bk[r]+2][2*brow[r]] = make_float2(vb[r].z, vb[r].z);
            *(float2*)&sBd[bk[r]+3][2*brow[r]] = make_float2(vb[r].w, vb[r].w);
        }
        __syncthreads();

#pragma unroll
        for (int kk = 0; kk < 32; kk++) {
            const ulonglong2 a01 = *(const ulonglong2*)&sA[kk][ty*8];
            const ulonglong2 a23 = *(const ulonglong2*)&sA[kk][ty*8 + 4];
            const ulonglong2 b01 = *(const ulonglong2*)&sBd[kk][tx*8];
            const ulonglong2 b23 = *(const ulonglong2*)&sBd[kk][tx*8 + 4];
            const u64p wd = swd[kc + kk];
            u64p a[4] = {a01.x, a01.y, a23.x, a23.y};
            u64p bd[4] = {b01.x, b01.y, b23.x, b23.y};
#pragma unroll
            for (int p = 0; p < 4; p++)
#pragma unroll
                for (int j = 0; j < 4; j++)
                    acc[p][j] = f2_fma(f2_relu(f2_add(a[p], bd[j])), wd, acc[p][j]);
        }
        __syncthreads();
    }

    float* Pd = P + ((size_t)(s*BB + b) * LL * LL);
#pragma unroll
    for (int p = 0; p < 4; p++) {
        float lo[4], hi[4];
#pragma unroll
        for (int j = 0; j < 4; j++) f2_unpack(acc[p][j], lo[j], hi[j]);
        const int r0 = i0 + ty*8 + 2*p;
        *(float4*)&Pd[(size_t)(r0+0) * LL + j0 + tx*4] = make_float4(lo[0], lo[1], lo[2], lo[3]);
        *(float4*)&Pd[(size_t)(r0+1) * LL + j0 + tx*4] = make_float4(hi[0], hi[1], hi[2], hi[3]);
    }
}

// =========================================================================
// K5: combine partials: out = sigmoid(P0 + P1 + P2 + P3 + b2)
// =========================================================================
__global__ __launch_bounds__(256) void combine_kernel(
    const float* __restrict__ P, const float* __restrict__ b2,
    float* __restrict__ out)
{
    const size_t n = (size_t)BB * LL * LL;
    const size_t idx = ((size_t)blockIdx.x * 256 + threadIdx.x) * 4;
    if (idx >= n) return;
    const float bias = b2[0];
    float4 p0 = *(const float4*)&P[idx];
    float4 p1 = *(const float4*)&P[n + idx];
    float4 p2 = *(const float4*)&P[2*n + idx];
    float4 p3 = *(const float4*)&P[3*n + idx];
    float4 o;
    o.x = 1.0f / (1.0f + __expf(-(p0.x + p1.x + p2.x + p3.x + bias)));
    o.y = 1.0f / (1.0f + __expf(-(p0.y + p1.y + p2.y + p3.y + bias)));
    o.z = 1.0f / (1.0f + __expf(-(p0.z + p1.z + p2.z + p3.z + bias)));
    o.w = 1.0f / (1.0f + __expf(-(p0.w + p1.w + p2.w + p3.w + bias)));
    *(float4*)&out[n + idx] = o;
}

// =========================================================================
extern "C" void kernel_launch(void* const* d_in, const int* in_sizes, int n_in,
                              void* d_out, int out_size)
{
    const float* e1  = (const float*)d_in[0];  // (B,L1,H)
    const float* e2  = (const float*)d_in[1];  // (B,L2,H)
    const float* ipw = (const float*)d_in[2];  // (3H,H)
    const float* ipb = (const float*)d_in[3];  // (3H,)
    const float* W1  = (const float*)d_in[4];  // (H,2H)
    const float* b1  = (const float*)d_in[5];  // (H,)
    const float* W2  = (const float*)d_in[6];  // (1,H)
    const float* b2  = (const float*)d_in[7];  // (1,)
    float* out = (float*)d_out;                // [attn (B,L1,L2)] ++ [match (B,L1,L2)]

    float* P;
    cudaGetSymbolAddress((void**)&P, g_logits);   // reuse logits buffer for partials

    proj_kernel   <<<dim3(HD/128, (BB*LL)/64, 4), 128>>>(e1, e2, ipw, ipb, W1, b1);
    logits_kernel <<<dim3(LL/128, LL/64, BB*NHEAD), 128>>>();
    softmax_mean_kernel<<<BB*LL, 256>>>(out);
    match_partial_kernel<<<dim3(LL/64, LL/128, BB*4), 256>>>(W2, P);
    combine_kernel<<<(BB*LL*LL/4 + 255)/256, 256>>>(P, b2, out);
}

// round 8
// speedup vs baseline: 1.4551x; 1.4551x over previous
#include <cuda_runtime.h>
#include <math.h>

#define HD 256      // hidden dim
#define BB 2        // batch
#define LL 512      // seq len (L1 == L2)
#define NHEAD 8
#define DHEAD 32

// ---------------- scratch (device globals; no allocation) ----------------
__device__ float g_q [BB*LL*HD];                 // 1 MB
__device__ float g_k [BB*LL*HD];                 // 1 MB
__device__ float g_h1[BB*LL*HD];                 // 1 MB (includes +b1)
__device__ float g_h2[BB*LL*HD];                 // 1 MB
__device__ float g_logits[(size_t)BB*NHEAD*LL*LL]; // 16 MB; reused for match partials

// ---------------- packed fp32x2 helpers (Blackwell) ----------------
typedef unsigned long long u64p;

__device__ __forceinline__ u64p f2_pack(float lo, float hi) {
    u64p r; asm("mov.b64 %0, {%1, %2};" : "=l"(r) : "f"(lo), "f"(hi)); return r;
}
__device__ __forceinline__ void f2_unpack(u64p p, float& lo, float& hi) {
    asm("mov.b64 {%0, %1}, %2;" : "=f"(lo), "=f"(hi) : "l"(p));
}
__device__ __forceinline__ u64p f2_fma(u64p a, u64p b, u64p c) {
    u64p d; asm("fma.rn.f32x2 %0, %1, %2, %3;" : "=l"(d) : "l"(a), "l"(b), "l"(c)); return d;
}
__device__ __forceinline__ u64p f2_add(u64p a, u64p b) {
    u64p d; asm("add.rn.f32x2 %0, %1, %2;" : "=l"(d) : "l"(a), "l"(b)); return d;
}
__device__ __forceinline__ u64p f2_relu(u64p x) {
    float lo, hi; f2_unpack(x, lo, hi);
    lo = fmaxf(lo, 0.0f); hi = fmaxf(hi, 0.0f);
    u64p r; asm("mov.b64 %0, {%1, %2};" : "=l"(r) : "f"(lo), "f"(hi)); return r;
}

// =========================================================================
// K1: projections (R4 version).  job z: 0=q 1=k 2=h1(+b1) 3=h2
// 64x64 tile, 256 threads, 4x4/thread, FFMA2-packed along the o-dim.
// grid (4, 16, 4) = 256 blocks.
// =========================================================================
__global__ __launch_bounds__(256) void proj_kernel(
    const float* __restrict__ e1, const float* __restrict__ e2,
    const float* __restrict__ ipw, const float* __restrict__ ipb,
    const float* __restrict__ W1,  const float* __restrict__ b1)
{
    const int job = blockIdx.z;
    const float* A; const float* W; const float* bias; int ldw; float* C;
    if (job == 0)      { A = e1; W = ipw;           bias = ipb;      ldw = HD;   C = g_q;  }
    else if (job == 1) { A = e2; W = ipw + HD*HD;   bias = ipb + HD; ldw = HD;   C = g_k;  }
    else if (job == 2) { A = e1; W = W1;            bias = b1;       ldw = 2*HD; C = g_h1; }
    else               { A = e2; W = W1 + HD;       bias = nullptr;  ldw = 2*HD; C = g_h2; }

    const int i0 = blockIdx.y * 64;
    const int j0 = blockIdx.x * 64;

    __shared__ __align__(16) float sA[32][68];
    __shared__ __align__(16) float sW[32][68];

    const int tid = threadIdx.x;
    const int tx = tid & 15, ty = tid >> 4;

    u64p acc[4][2] = {};   // 4 rows x (2 packed col-pairs)

    for (int k0 = 0; k0 < HD; k0 += 32) {
#pragma unroll
        for (int r = 0; r < 8; r++) {
            int idx = r * 256 + tid;
            int m = idx >> 5, kk = idx & 31;
            sA[kk][m] = A[(size_t)(i0 + m) * HD  + k0 + kk];
            sW[kk][m] = W[(size_t)(j0 + m) * ldw + k0 + kk];
        }
        __syncthreads();
#pragma unroll
        for (int kk = 0; kk < 32; kk++) {
            const float4 a4 = *(const float4*)&sA[kk][ty*4];
            const ulonglong2 wp = *(const ulonglong2*)&sW[kk][tx*4];
            u64p ad0 = f2_pack(a4.x, a4.x);
            u64p ad1 = f2_pack(a4.y, a4.y);
            u64p ad2 = f2_pack(a4.z, a4.z);
            u64p ad3 = f2_pack(a4.w, a4.w);
            acc[0][0] = f2_fma(ad0, wp.x, acc[0][0]);
            acc[0][1] = f2_fma(ad0, wp.y, acc[0][1]);
            acc[1][0] = f2_fma(ad1, wp.x, acc[1][0]);
            acc[1][1] = f2_fma(ad1, wp.y, acc[1][1]);
            acc[2][0] = f2_fma(ad2, wp.x, acc[2][0]);
            acc[2][1] = f2_fma(ad2, wp.y, acc[2][1]);
            acc[3][0] = f2_fma(ad3, wp.x, acc[3][0]);
            acc[3][1] = f2_fma(ad3, wp.y, acc[3][1]);
        }
        __syncthreads();
    }

    float bv[4] = {0.f, 0.f, 0.f, 0.f};
    if (bias) {
#pragma unroll
        for (int v = 0; v < 4; v++) bv[v] = bias[j0 + tx*4 + v];
    }
#pragma unroll
    for (int u = 0; u < 4; u++) {
        float c0, c1, c2, c3;
        f2_unpack(acc[u][0], c0, c1);
        f2_unpack(acc[u][1], c2, c3);
        float4 o4 = make_float4(c0 + bv[0], c1 + bv[1], c2 + bv[2], c3 + bv[3]);
        *(float4*)&C[(size_t)(i0 + ty*4 + u) * HD + j0 + tx*4] = o4;
    }
}

// =========================================================================
// K2: logits (R4 version). grid (8,8,16); tile 64x64, K=32, FFMA2-packed.
// =========================================================================
__global__ __launch_bounds__(256) void logits_kernel()
{
    const int bh = blockIdx.z;
    const int b  = bh >> 3, h = bh & 7;
    const float* Q  = g_q + (size_t)b * LL * HD + h * DHEAD;
    const float* Kp = g_k + (size_t)b * LL * HD + h * DHEAD;
    float* C = g_logits + (size_t)bh * LL * LL;

    const int i0 = blockIdx.y * 64;
    const int j0 = blockIdx.x * 64;

    __shared__ __align__(16) float sA[32][68];
    __shared__ __align__(16) float sW[32][68];

    const int tid = threadIdx.x;
    const int tx = tid & 15, ty = tid >> 4;

#pragma unroll
    for (int r = 0; r < 8; r++) {
        int idx = r * 256 + tid;
        int m = idx >> 5, kk = idx & 31;
        sA[kk][m] = Q [(size_t)(i0 + m) * HD + kk];
        sW[kk][m] = Kp[(size_t)(j0 + m) * HD + kk];
    }
    __syncthreads();

    u64p acc[4][2] = {};
#pragma unroll
    for (int kk = 0; kk < 32; kk++) {
        const float4 a4 = *(const float4*)&sA[kk][ty*4];
        const ulonglong2 wp = *(const ulonglong2*)&sW[kk][tx*4];
        u64p ad0 = f2_pack(a4.x, a4.x);
        u64p ad1 = f2_pack(a4.y, a4.y);
        u64p ad2 = f2_pack(a4.z, a4.z);
        u64p ad3 = f2_pack(a4.w, a4.w);
        acc[0][0] = f2_fma(ad0, wp.x, acc[0][0]);
        acc[0][1] = f2_fma(ad0, wp.y, acc[0][1]);
        acc[1][0] = f2_fma(ad1, wp.x, acc[1][0]);
        acc[1][1] = f2_fma(ad1, wp.y, acc[1][1]);
        acc[2][0] = f2_fma(ad2, wp.x, acc[2][0]);
        acc[2][1] = f2_fma(ad2, wp.y, acc[2][1]);
        acc[3][0] = f2_fma(ad3, wp.x, acc[3][0]);
        acc[3][1] = f2_fma(ad3, wp.y, acc[3][1]);
    }

    const float scale = 0.1767766952966369f; // 1/sqrt(32)
#pragma unroll
    for (int u = 0; u < 4; u++) {
        float c0, c1, c2, c3;
        f2_unpack(acc[u][0], c0, c1);
        f2_unpack(acc[u][1], c2, c3);
        float4 o4 = make_float4(c0*scale, c1*scale, c2*scale, c3*scale);
        *(float4*)&C[(size_t)(i0 + ty*4 + u) * LL + j0 + tx*4] = o4;
    }
}

// =========================================================================
// K3: softmax + head-mean.  One block per (b,i); warp h owns head h's row.
// =========================================================================
__global__ __launch_bounds__(256) void softmax_mean_kernel(float* __restrict__ out)
{
    const int b = blockIdx.x >> 9;
    const int i = blockIdx.x & 511;
    const int wid  = threadIdx.x >> 5;
    const int lane = threadIdx.x & 31;

    __shared__ float p[8][512];

    const float* row = g_logits + ((size_t)(b*8 + wid) * LL + i) * LL;

    float v[16];
    float mx = -1e30f;
#pragma unroll
    for (int r = 0; r < 16; r++) {
        v[r] = row[lane + 32*r];
        mx = fmaxf(mx, v[r]);
    }
#pragma unroll
    for (int o = 16; o; o >>= 1) mx = fmaxf(mx, __shfl_xor_sync(0xffffffffu, mx, o));

    float s = 0.0f;
#pragma unroll
    for (int r = 0; r < 16; r++) { v[r] = __expf(v[r] - mx); s += v[r]; }
#pragma unroll
    for (int o = 16; o; o >>= 1) s += __shfl_xor_sync(0xffffffffu, s, o);
    const float inv = 1.0f / s;

#pragma unroll
    for (int r = 0; r < 16; r++) p[wid][lane + 32*r] = v[r] * inv;

    __syncthreads();

    const int t = threadIdx.x;
    const size_t o = ((size_t)b * LL + i) * LL;
#pragma unroll
    for (int jj = 0; jj < 2; jj++) {
        int j = t + jj * 256;
        float a = 0.0f;
#pragma unroll
        for (int h = 0; h < 8; h++) a += p[h][j];
        out[o + j] = a * 0.125f;
    }
}

// =========================================================================
// K4: match partials over 4 channel-splits of 64.
// P[(s*BB+b)*LL*LL + i*LL + j] = sum_{c in split} relu(h1[i,c]+h2[j,c])*w2[c]
// Block tile 64i x 64j, 256 threads, 4i x 4j/thread (i-packed pairs).
// A natural pairs, B duplicated, w2 duplicated. grid (8, 8, 8) = 512 blocks.
// =========================================================================
__global__ __launch_bounds__(256) void match_partial_kernel(
    const float* __restrict__ W2, float* __restrict__ P)
{
    const int bz = blockIdx.z;
    const int b  = bz >> 2;
    const int s  = bz & 3;
    const int i0 = blockIdx.y * 64;
    const int j0 = blockIdx.x * 64;
    const int c0 = s * 64;

    const float* A  = g_h1 + (size_t)b * LL * HD;
    const float* Bm = g_h2 + (size_t)b * LL * HD;

    __shared__ __align__(16) float sA [32][68];   // [kk][i], 64 used (natural)
    __shared__ __align__(16) float sBd[32][132];  // [kk][2j], 128 used (dup)
    __shared__ __align__(16) float2 sw2d[64];     // (w,w)

    const int tid = threadIdx.x;
    const int ty = tid >> 4;       // 0..15 -> 4 rows (2 pairs)
    const int tx = tid & 15;       // 0..15 -> 4 cols

    if (tid < 64) { float w = W2[c0 + tid]; sw2d[tid] = make_float2(w, w); }
    const u64p* swd = (const u64p*)sw2d;

    const int lm  = tid >> 3;        // 0..31
    const int lk4 = (tid & 7) * 4;   // 0..28

    u64p acc[2][4] = {};   // [i-pair][j]

    for (int kc = 0; kc < 64; kc += 32) {
        const int k0 = c0 + kc;
        float4 va0 = *(const float4*)&A [(size_t)(i0 + lm)      * HD + k0 + lk4];
        float4 va1 = *(const float4*)&A [(size_t)(i0 + 32 + lm) * HD + k0 + lk4];
        float4 vb0 = *(const float4*)&Bm[(size_t)(j0 + lm)      * HD + k0 + lk4];
        float4 vb1 = *(const float4*)&Bm[(size_t)(j0 + 32 + lm) * HD + k0 + lk4];
        __syncthreads();
        sA[lk4+0][lm]    = va0.x; sA[lk4+1][lm]    = va0.y; sA[lk4+2][lm]    = va0.z; sA[lk4+3][lm]    = va0.w;
        sA[lk4+0][32+lm] = va1.x; sA[lk4+1][32+lm] = va1.y; sA[lk4+2][32+lm] = va1.z; sA[lk4+3][32+lm] = va1.w;
        *(float2*)&sBd[lk4+0][2*lm]    = make_float2(vb0.x, vb0.x);
        *(float2*)&sBd[lk4+1][2*lm]    = make_float2(vb0.y, vb0.y);
        *(float2*)&sBd[lk4+2][2*lm]    = make_float2(vb0.z, vb0.z);
        *(float2*)&sBd[lk4+3][2*lm]    = make_float2(vb0.w, vb0.w);
        *(float2*)&sBd[lk4+0][64+2*lm] = make_float2(vb1.x, vb1.x);
        *(float2*)&sBd[lk4+1][64+2*lm] = make_float2(vb1.y, vb1.y);
        *(float2*)&sBd[lk4+2][64+2*lm] = make_float2(vb1.z, vb1.z);
        *(float2*)&sBd[lk4+3][64+2*lm] = make_float2(vb1.w, vb1.w);
        __syncthreads();

#pragma unroll
        for (int kk = 0; kk < 32; kk++) {
            const ulonglong2 a01 = *(const ulonglong2*)&sA [kk][ty*4];  // pairs (r0,r1),(r2,r3)
            const ulonglong2 b01 = *(const ulonglong2*)&sBd[kk][tx*8];  // (b0,b0),(b1,b1)
            const ulonglong2 b23 = *(const ulonglong2*)&sBd[kk][tx*8 + 4];
            const u64p wd = swd[kc + kk];
            u64p a[2]  = {a01.x, a01.y};
            u64p bd[4] = {b01.x, b01.y, b23.x, b23.y};
#pragma unroll
            for (int p = 0; p < 2; p++)
#pragma unroll
                for (int j = 0; j < 4; j++)
                    acc[p][j] = f2_fma(f2_relu(f2_add(a[p], bd[j])), wd, acc[p][j]);
        }
        __syncthreads();
    }

    float* Pd = P + ((size_t)(s*BB + b) * LL * LL);
#pragma unroll
    for (int p = 0; p < 2; p++) {
        float lo[4], hi[4];
#pragma unroll
        for (int j = 0; j < 4; j++) f2_unpack(acc[p][j], lo[j], hi[j]);
        const int r0 = i0 + ty*4 + 2*p;
        *(float4*)&Pd[(size_t)(r0+0) * LL + j0 + tx*4] = make_float4(lo[0], lo[1], lo[2], lo[3]);
        *(float4*)&Pd[(size_t)(r0+1) * LL + j0 + tx*4] = make_float4(hi[0], hi[1], hi[2], hi[3]);
    }
}

// =========================================================================
// K5: combine partials: out = sigmoid(P0 + P1 + P2 + P3 + b2)
// =========================================================================
__global__ __launch_bounds__(256) void combine_kernel(
    const float* __restrict__ P, const float* __restrict__ b2,
    float* __restrict__ out)
{
    const size_t n = (size_t)BB * LL * LL;
    const size_t idx = ((size_t)blockIdx.x * 256 + threadIdx.x) * 4;
    if (idx >= n) return;
    const float bias = b2[0];
    float4 p0 = *(const float4*)&P[idx];
    float4 p1 = *(const float4*)&P[n + idx];
    float4 p2 = *(const float4*)&P[2*n + idx];
    float4 p3 = *(const float4*)&P[3*n + idx];
    float4 o;
    o.x = 1.0f / (1.0f + __expf(-(p0.x + p1.x + p2.x + p3.x + bias)));
    o.y = 1.0f / (1.0f + __expf(-(p0.y + p1.y + p2.y + p3.y + bias)));
    o.z = 1.0f / (1.0f + __expf(-(p0.z + p1.z + p2.z + p3.z + bias)));
    o.w = 1.0f / (1.0f + __expf(-(p0.w + p1.w + p2.w + p3.w + bias)));
    *(float4*)&out[n + idx] = o;
}

// =========================================================================
extern "C" void kernel_launch(void* const* d_in, const int* in_sizes, int n_in,
                              void* d_out, int out_size)
{
    const float* e1  = (const float*)d_in[0];  // (B,L1,H)
    const float* e2  = (const float*)d_in[1];  // (B,L2,H)
    const float* ipw = (const float*)d_in[2];  // (3H,H)
    const float* ipb = (const float*)d_in[3];  // (3H,)
    const float* W1  = (const float*)d_in[4];  // (H,2H)
    const float* b1  = (const float*)d_in[5];  // (H,)
    const float* W2  = (const float*)d_in[6];  // (1,H)
    const float* b2  = (const float*)d_in[7];  // (1,)
    float* out = (float*)d_out;                // [attn (B,L1,L2)] ++ [match (B,L1,L2)]

    float* P;
    cudaGetSymbolAddress((void**)&P, g_logits);   // reuse logits buffer for partials

    proj_kernel   <<<dim3(HD/64, (BB*LL)/64, 4), 256>>>(e1, e2, ipw, ipb, W1, b1);
    logits_kernel <<<dim3(LL/64, LL/64, BB*NHEAD), 256>>>();
    softmax_mean_kernel<<<BB*LL, 256>>>(out);
    match_partial_kernel<<<dim3(LL/64, LL/64, BB*4), 256>>>(W2, P);
    combine_kernel<<<(BB*LL*LL/4 + 255)/256, 256>>>(P, b2, out);
}

// round 9
// speedup vs baseline: 1.7023x; 1.1699x over previous
#include <cuda_runtime.h>
#include <math.h>

#define HD 256      // hidden dim
#define BB 2        // batch
#define LL 512      // seq len (L1 == L2)
#define NHEAD 8
#define DHEAD 32
#define NSPLIT 8    // match channel splits (32 channels each)

// ---------------- scratch (device globals; no allocation) ----------------
__device__ float g_q [BB*LL*HD];                 // 1 MB
__device__ float g_k [BB*LL*HD];                 // 1 MB
__device__ float g_h1[BB*LL*HD];                 // 1 MB (includes +b1)
__device__ float g_h2[BB*LL*HD];                 // 1 MB
__device__ float g_logits[(size_t)BB*NHEAD*LL*LL]; // 16 MB; reused for match partials (16 planes)
__device__ float g_alpha[BB*LL];                 // sum_c (w/2) h1[b,i,c]
__device__ float g_beta [BB*LL];                 // sum_c (w/2) h2[b,j,c]

// ---------------- packed fp32x2 helpers (Blackwell) ----------------
typedef unsigned long long u64p;

__device__ __forceinline__ u64p f2_pack(float lo, float hi) {
    u64p r; asm("mov.b64 %0, {%1, %2};" : "=l"(r) : "f"(lo), "f"(hi)); return r;
}
__device__ __forceinline__ void f2_unpack(u64p p, float& lo, float& hi) {
    asm("mov.b64 {%0, %1}, %2;" : "=f"(lo), "=f"(hi) : "l"(p));
}
__device__ __forceinline__ u64p f2_fma(u64p a, u64p b, u64p c) {
    u64p d; asm("fma.rn.f32x2 %0, %1, %2, %3;" : "=l"(d) : "l"(a), "l"(b), "l"(c)); return d;
}
__device__ __forceinline__ u64p f2_add(u64p a, u64p b) {
    u64p d; asm("add.rn.f32x2 %0, %1, %2;" : "=l"(d) : "l"(a), "l"(b)); return d;
}
__device__ __forceinline__ u64p f2_abs(u64p x) {
    float lo, hi; f2_unpack(x, lo, hi);
    lo = fabsf(lo); hi = fabsf(hi);
    return f2_pack(lo, hi);
}

// =========================================================================
// K1: projections (R4/R8 version).  job z: 0=q 1=k 2=h1(+b1) 3=h2
// 64x64 tile, 256 threads, 4x4/thread, FFMA2-packed along the o-dim.
// =========================================================================
__global__ __launch_bounds__(256) void proj_kernel(
    const float* __restrict__ e1, const float* __restrict__ e2,
    const float* __restrict__ ipw, const float* __restrict__ ipb,
    const float* __restrict__ W1,  const float* __restrict__ b1)
{
    const int job = blockIdx.z;
    const float* A; const float* W; const float* bias; int ldw; float* C;
    if (job == 0)      { A = e1; W = ipw;           bias = ipb;      ldw = HD;   C = g_q;  }
    else if (job == 1) { A = e2; W = ipw + HD*HD;   bias = ipb + HD; ldw = HD;   C = g_k;  }
    else if (job == 2) { A = e1; W = W1;            bias = b1;       ldw = 2*HD; C = g_h1; }
    else               { A = e2; W = W1 + HD;       bias = nullptr;  ldw = 2*HD; C = g_h2; }

    const int i0 = blockIdx.y * 64;
    const int j0 = blockIdx.x * 64;

    __shared__ __align__(16) float sA[32][68];
    __shared__ __align__(16) float sW[32][68];

    const int tid = threadIdx.x;
    const int tx = tid & 15, ty = tid >> 4;

    u64p acc[4][2] = {};

    for (int k0 = 0; k0 < HD; k0 += 32) {
#pragma unroll
        for (int r = 0; r < 8; r++) {
            int idx = r * 256 + tid;
            int m = idx >> 5, kk = idx & 31;
            sA[kk][m] = A[(size_t)(i0 + m) * HD  + k0 + kk];
            sW[kk][m] = W[(size_t)(j0 + m) * ldw + k0 + kk];
        }
        __syncthreads();
#pragma unroll
        for (int kk = 0; kk < 32; kk++) {
            const float4 a4 = *(const float4*)&sA[kk][ty*4];
            const ulonglong2 wp = *(const ulonglong2*)&sW[kk][tx*4];
            u64p ad0 = f2_pack(a4.x, a4.x);
            u64p ad1 = f2_pack(a4.y, a4.y);
            u64p ad2 = f2_pack(a4.z, a4.z);
            u64p ad3 = f2_pack(a4.w, a4.w);
            acc[0][0] = f2_fma(ad0, wp.x, acc[0][0]);
            acc[0][1] = f2_fma(ad0, wp.y, acc[0][1]);
            acc[1][0] = f2_fma(ad1, wp.x, acc[1][0]);
            acc[1][1] = f2_fma(ad1, wp.y, acc[1][1]);
            acc[2][0] = f2_fma(ad2, wp.x, acc[2][0]);
            acc[2][1] = f2_fma(ad2, wp.y, acc[2][1]);
            acc[3][0] = f2_fma(ad3, wp.x, acc[3][0]);
            acc[3][1] = f2_fma(ad3, wp.y, acc[3][1]);
        }
        __syncthreads();
    }

    float bv[4] = {0.f, 0.f, 0.f, 0.f};
    if (bias) {
#pragma unroll
        for (int v = 0; v < 4; v++) bv[v] = bias[j0 + tx*4 + v];
    }
#pragma unroll
    for (int u = 0; u < 4; u++) {
        float c0, c1, c2, c3;
        f2_unpack(acc[u][0], c0, c1);
        f2_unpack(acc[u][1], c2, c3);
        float4 o4 = make_float4(c0 + bv[0], c1 + bv[1], c2 + bv[2], c3 + bv[3]);
        *(float4*)&C[(size_t)(i0 + ty*4 + u) * HD + j0 + tx*4] = o4;
    }
}

// =========================================================================
// K2: logits (R4/R8 version). grid (8,8,16); tile 64x64, K=32.
// =========================================================================
__global__ __launch_bounds__(256) void logits_kernel()
{
    const int bh = blockIdx.z;
    const int b  = bh >> 3, h = bh & 7;
    const float* Q  = g_q + (size_t)b * LL * HD + h * DHEAD;
    const float* Kp = g_k + (size_t)b * LL * HD + h * DHEAD;
    float* C = g_logits + (size_t)bh * LL * LL;

    const int i0 = blockIdx.y * 64;
    const int j0 = blockIdx.x * 64;

    __shared__ __align__(16) float sA[32][68];
    __shared__ __align__(16) float sW[32][68];

    const int tid = threadIdx.x;
    const int tx = tid & 15, ty = tid >> 4;

#pragma unroll
    for (int r = 0; r < 8; r++) {
        int idx = r * 256 + tid;
        int m = idx >> 5, kk = idx & 31;
        sA[kk][m] = Q [(size_t)(i0 + m) * HD + kk];
        sW[kk][m] = Kp[(size_t)(j0 + m) * HD + kk];
    }
    __syncthreads();

    u64p acc[4][2] = {};
#pragma unroll
    for (int kk = 0; kk < 32; kk++) {
        const float4 a4 = *(const float4*)&sA[kk][ty*4];
        const ulonglong2 wp = *(const ulonglong2*)&sW[kk][tx*4];
        u64p ad0 = f2_pack(a4.x, a4.x);
        u64p ad1 = f2_pack(a4.y, a4.y);
        u64p ad2 = f2_pack(a4.z, a4.z);
        u64p ad3 = f2_pack(a4.w, a4.w);
        acc[0][0] = f2_fma(ad0, wp.x, acc[0][0]);
        acc[0][1] = f2_fma(ad0, wp.y, acc[0][1]);
        acc[1][0] = f2_fma(ad1, wp.x, acc[1][0]);
        acc[1][1] = f2_fma(ad1, wp.y, acc[1][1]);
        acc[2][0] = f2_fma(ad2, wp.x, acc[2][0]);
        acc[2][1] = f2_fma(ad2, wp.y, acc[2][1]);
        acc[3][0] = f2_fma(ad3, wp.x, acc[3][0]);
        acc[3][1] = f2_fma(ad3, wp.y, acc[3][1]);
    }

    const float scale = 0.1767766952966369f; // 1/sqrt(32)
#pragma unroll
    for (int u = 0; u < 4; u++) {
        float c0, c1, c2, c3;
        f2_unpack(acc[u][0], c0, c1);
        f2_unpack(acc[u][1], c2, c3);
        float4 o4 = make_float4(c0*scale, c1*scale, c2*scale, c3*scale);
        *(float4*)&C[(size_t)(i0 + ty*4 + u) * LL + j0 + tx*4] = o4;
    }
}

// =========================================================================
// K3: softmax + head-mean + alpha/beta.
// One block per (b,i); warp h owns head h's row. Additionally computes
// alpha[b,i] = sum_c (w2[c]/2) h1[b,i,c], beta[b,i] = sum_c (w2[c]/2) h2[b,i,c].
// =========================================================================
__global__ __launch_bounds__(256) void softmax_mean_kernel(
    const float* __restrict__ W2, float* __restrict__ out)
{
    const int b = blockIdx.x >> 9;
    const int i = blockIdx.x & 511;
    const int wid  = threadIdx.x >> 5;
    const int lane = threadIdx.x & 31;
    const int t = threadIdx.x;

    __shared__ float p[8][512];
    __shared__ float reda[8], redb[8];

    const float* row = g_logits + ((size_t)(b*8 + wid) * LL + i) * LL;

    float v[16];
    float mx = -1e30f;
#pragma unroll
    for (int r = 0; r < 16; r++) {
        v[r] = row[lane + 32*r];
        mx = fmaxf(mx, v[r]);
    }
#pragma unroll
    for (int o = 16; o; o >>= 1) mx = fmaxf(mx, __shfl_xor_sync(0xffffffffu, mx, o));

    float s = 0.0f;
#pragma unroll
    for (int r = 0; r < 16; r++) { v[r] = __expf(v[r] - mx); s += v[r]; }
#pragma unroll
    for (int o = 16; o; o >>= 1) s += __shfl_xor_sync(0xffffffffu, s, o);
    const float inv = 1.0f / s;

#pragma unroll
    for (int r = 0; r < 16; r++) p[wid][lane + 32*r] = v[r] * inv;

    // ---- alpha/beta partials (this block owns row (b,i) of h1 and h2) ----
    {
        const float wh = 0.5f * W2[t];
        float pa = g_h1[((size_t)b*LL + i)*HD + t] * wh;
        float pb = g_h2[((size_t)b*LL + i)*HD + t] * wh;
#pragma unroll
        for (int o = 16; o; o >>= 1) {
            pa += __shfl_xor_sync(0xffffffffu, pa, o);
            pb += __shfl_xor_sync(0xffffffffu, pb, o);
        }
        if (lane == 0) { reda[wid] = pa; redb[wid] = pb; }
    }

    __syncthreads();

    const size_t o = ((size_t)b * LL + i) * LL;
#pragma unroll
    for (int jj = 0; jj < 2; jj++) {
        int j = t + jj * 256;
        float a = 0.0f;
#pragma unroll
        for (int h = 0; h < 8; h++) a += p[h][j];
        out[o + j] = a * 0.125f;
    }

    if (t < 16) {
        float va = (t < 8) ? reda[t] : redb[t - 8];
#pragma unroll
        for (int oo = 4; oo; oo >>= 1) va += __shfl_xor_sync(0xffffffffu, va, oo);
        if (t == 0) g_alpha[b*LL + i] = va;
        if (t == 8) g_beta [b*LL + i] = va;
    }
}

// =========================================================================
// K4: match partials over 8 channel-splits of 32.
// P[(s*BB+b)*LL*LL + i*LL + j] = sum_{c in split} (w2[c]/2) * |h1[i,c]+h2[j,c]|
// Block tile 64i x 64j, 128 threads, 8i x 4j/thread (i-packed pairs).
// A natural pairs, B duplicated (amortized over Ti=8), w2/2 duplicated.
// grid (8, 8, 16) = 1024 blocks of 4 warps.
// =========================================================================
__global__ __launch_bounds__(128) void match_partial_kernel(
    const float* __restrict__ W2, float* __restrict__ P)
{
    const int bz = blockIdx.z;
    const int b  = bz & 1;
    const int s  = bz >> 1;
    const int i0 = blockIdx.y * 64;
    const int j0 = blockIdx.x * 64;
    const int c0 = s * 32;

    const float* A  = g_h1 + (size_t)b * LL * HD + c0;
    const float* Bm = g_h2 + (size_t)b * LL * HD + c0;

    __shared__ __align__(16) float sA [32][68];   // [kk][i], 64 used (natural)
    __shared__ __align__(16) float sBd[32][132];  // [kk][2j], 128 used (dup)
    __shared__ __align__(16) float2 sw2d[32];     // (w/2, w/2)

    const int tid = threadIdx.x;
    const int ty = tid >> 4;       // 0..7  -> rows ty*8 .. ty*8+7 (4 pairs)
    const int tx = tid & 15;       // 0..15 -> cols tx*4 .. tx*4+3

    if (tid < 32) { float w = 0.5f * W2[c0 + tid]; sw2d[tid] = make_float2(w, w); }
    const u64p* swd = (const u64p*)sw2d;

    // loaders: 64 rows x 32 k = 512 float4; 128 threads x 4
    {
        float4 va[4], vb[4];
        int arow[4], ak[4];
#pragma unroll
        for (int r = 0; r < 4; r++) {
            int pidx = tid + r * 128;
            arow[r] = pidx >> 3; ak[r] = (pidx & 7) << 2;
            va[r] = *(const float4*)&A [(size_t)(i0 + arow[r]) * HD + ak[r]];
            vb[r] = *(const float4*)&Bm[(size_t)(j0 + arow[r]) * HD + ak[r]];
        }
#pragma unroll
        for (int r = 0; r < 4; r++) {
            sA[ak[r]+0][arow[r]] = va[r].x; sA[ak[r]+1][arow[r]] = va[r].y;
            sA[ak[r]+2][arow[r]] = va[r].z; sA[ak[r]+3][arow[r]] = va[r].w;
            *(float2*)&sBd[ak[r]+0][2*arow[r]] = make_float2(vb[r].x, vb[r].x);
            *(float2*)&sBd[ak[r]+1][2*arow[r]] = make_float2(vb[r].y, vb[r].y);
            *(float2*)&sBd[ak[r]+2][2*arow[r]] = make_float2(vb[r].z, vb[r].z);
            *(float2*)&sBd[ak[r]+3][2*arow[r]] = make_float2(vb[r].w, vb[r].w);
        }
    }
    __syncthreads();

    u64p acc[4][4] = {};   // [i-pair p][j]

#pragma unroll
    for (int kk = 0; kk < 32; kk++) {
        const ulonglong2 a01 = *(const ulonglong2*)&sA [kk][ty*8];      // pairs (r0,r1),(r2,r3)
        const ulonglong2 a23 = *(const ulonglong2*)&sA [kk][ty*8 + 4];  // pairs (r4,r5),(r6,r7)
        const ulonglong2 b01 = *(const ulonglong2*)&sBd[kk][tx*8];      // (b0,b0),(b1,b1)
        const ulonglong2 b23 = *(const ulonglong2*)&sBd[kk][tx*8 + 4];  // (b2,b2),(b3,b3)
        const u64p wd = swd[kk];
        u64p a[4]  = {a01.x, a01.y, a23.x, a23.y};
        u64p bd[4] = {b01.x, b01.y, b23.x, b23.y};
#pragma unroll
        for (int p = 0; p < 4; p++)
#pragma unroll
            for (int j = 0; j < 4; j++)
                acc[p][j] = f2_fma(f2_abs(f2_add(a[p], bd[j])), wd, acc[p][j]);
    }

    float* Pd = P + ((size_t)(s*BB + b) * LL * LL);
#pragma unroll
    for (int p = 0; p < 4; p++) {
        float lo[4], hi[4];
#pragma unroll
        for (int j = 0; j < 4; j++) f2_unpack(acc[p][j], lo[j], hi[j]);
        const int r0 = i0 + ty*8 + 2*p;
        *(float4*)&Pd[(size_t)(r0+0) * LL + j0 + tx*4] = make_float4(lo[0], lo[1], lo[2], lo[3]);
        *(float4*)&Pd[(size_t)(r0+1) * LL + j0 + tx*4] = make_float4(hi[0], hi[1], hi[2], hi[3]);
    }
}

// =========================================================================
// K5: combine: out = sigmoid(alpha_i + beta_j + sum_s P_s + b2)
// =========================================================================
__global__ __launch_bounds__(256) void combine_kernel(
    const float* __restrict__ P, const float* __restrict__ b2,
    float* __restrict__ out)
{
    const size_t n = (size_t)BB * LL * LL;
    const size_t idx = ((size_t)blockIdx.x * 256 + threadIdx.x) * 4;
    if (idx >= n) return;

    const int b = (int)(idx >> 18);
    const int rem = (int)(idx & 262143);
    const int i = rem >> 9;
    const int j = rem & 511;

    float base = g_alpha[b*LL + i] + b2[0];
    float4 bt = *(const float4*)&g_beta[b*LL + j];

    float4 acc = make_float4(base + bt.x, base + bt.y, base + bt.z, base + bt.w);
#pragma unroll
    for (int s = 0; s < NSPLIT; s++) {
        float4 ps = *(const float4*)&P[(size_t)s * n + idx];
        acc.x += ps.x; acc.y += ps.y; acc.z += ps.z; acc.w += ps.w;
    }
    float4 o;
    o.x = 1.0f / (1.0f + __expf(-acc.x));
    o.y = 1.0f / (1.0f + __expf(-acc.y));
    o.z = 1.0f / (1.0f + __expf(-acc.z));
    o.w = 1.0f / (1.0f + __expf(-acc.w));
    *(float4*)&out[n + idx] = o;
}

// =========================================================================
extern "C" void kernel_launch(void* const* d_in, const int* in_sizes, int n_in,
                              void* d_out, int out_size)
{
    const float* e1  = (const float*)d_in[0];  // (B,L1,H)
    const float* e2  = (const float*)d_in[1];  // (B,L2,H)
    const float* ipw = (const float*)d_in[2];  // (3H,H)
    const float* ipb = (const float*)d_in[3];  // (3H,)
    const float* W1  = (const float*)d_in[4];  // (H,2H)
    const float* b1  = (const float*)d_in[5];  // (H,)
    const float* W2  = (const float*)d_in[6];  // (1,H)
    const float* b2  = (const float*)d_in[7];  // (1,)
    float* out = (float*)d_out;                // [attn (B,L1,L2)] ++ [match (B,L1,L2)]

    float* P;
    cudaGetSymbolAddress((void**)&P, g_logits);   // reuse logits buffer for partials

    proj_kernel   <<<dim3(HD/64, (BB*LL)/64, 4), 256>>>(e1, e2, ipw, ipb, W1, b1);
    logits_kernel <<<dim3(LL/64, LL/64, BB*NHEAD), 256>>>();
    softmax_mean_kernel<<<BB*LL, 256>>>(W2, out);
    match_partial_kernel<<<dim3(LL/64, LL/64, BB*NSPLIT), 128>>>(W2, P);
    combine_kernel<<<(unsigned)((BB*LL*LL/4 + 255)/256), 256>>>(P, b2, out);
}